// round 3
// baseline (speedup 1.0000x reference)
#include <cuda_runtime.h>
#include <cuda_fp16.h>
#include <mma.h>
#include <cstdint>
#include <cstddef>

using namespace nvcuda;

// Problem shape (fixed by setup_inputs)
static constexpr int M_DIM = 4096;
static constexpr int K_DIM = 4096;
static constexpr int N_DIM = 11008;

// Tiling
static constexpr int BM = 128;
static constexpr int BN = 128;
static constexpr int BK = 64;
// Strides keep every WMMA fragment pointer 32-byte aligned.
static constexpr int LDA = BK + 16;   // 80 halves  = 160 B (32B multiple)
static constexpr int LDB = BN + 16;   // 144 halves = 288 B (32B multiple)

// ---------------------------------------------------------------------------
// Fused GPTQ-4bit dequant + GEMM.
// HARNESS DTYPES: fp16 tensors are materialized as float32 by the harness.
//   x      : float32 [M, K]   (values exactly representable in fp16)
//   qweight: int32   [K/8, N] nibble j (shift 4*j) -> row k = kp*8 + j
//   qzeros : int32   [1, N/8] nibble (n%8) -> zero for col n; +1 per GPTQ
//   scales : float32 [1, N]   (values exactly representable in fp16)
//   out    : float32 [M, N]
// Compute: w(k,n) = fp16(q - zero) *fp16 scale(n); Y = X*W, fp32 accum,
// rounded through fp16 to match the reference's fp16 dot output.
// Block tile 128x128x64; 8 warps = 2(M) x 4(N), each warp 64x32 output
// (4x2 m16n16k16 WMMA tiles).
// ---------------------------------------------------------------------------
__global__ __launch_bounds__(256, 1)
void fused_gptq_gemm(const float* __restrict__ X,
                     const int*   __restrict__ qweight,
                     const int*   __restrict__ qzeros,
                     const float* __restrict__ scales,
                     float*       __restrict__ Y) {
    __shared__ __half sA[BM * LDA];   // 20480 B
    __shared__ __half sB[BK * LDB];   // 18432 B

    const int tid  = threadIdx.x;
    const int warp = tid >> 5;
    const int lane = tid & 31;
    const int wm   = warp >> 2;       // 0..1 (64-row slice)
    const int wn   = warp & 3;        // 0..3 (32-col slice)
    const int bm   = blockIdx.y * BM;
    const int bn   = blockIdx.x * BN;

    // Per-thread dequant column.
    const int col  = tid & 127;                 // 0..127
    const int gcol = bn + col;
    const int zp   = qzeros[gcol >> 3];
    const int zero = ((zp >> ((gcol & 7) * 4)) & 0xF) + 1;
    const __half s = __float2half_rn(scales[gcol]);   // exact (was fp16)

    wmma::fragment<wmma::accumulator, 16, 16, 16, float> acc[4][2];
#pragma unroll
    for (int i = 0; i < 4; i++)
#pragma unroll
        for (int j = 0; j < 2; j++)
            wmma::fill_fragment(acc[i][j], 0.0f);

    for (int k0 = 0; k0 < K_DIM; k0 += BK) {
        // --- Load A tile [BM x BK] f32 -> fp16 smem. 2048 float4, 8/thread ---
#pragma unroll
        for (int t = 0; t < 8; t++) {
            const int flat = (tid + t * 256) * 4;   // element index in tile
            const int r = flat >> 6;                // /64
            const int c = flat & 63;
            const float4 v = *reinterpret_cast<const float4*>(
                X + (size_t)(bm + r) * K_DIM + k0 + c);
            const __half2 h0 = __floats2half2_rn(v.x, v.y);
            const __half2 h1 = __floats2half2_rn(v.z, v.w);
            __half2* dst = reinterpret_cast<__half2*>(&sA[r * LDA + c]);
            dst[0] = h0;
            dst[1] = h1;
        }

        // --- Dequant B tile [BK x BN]: 8 packed rows x 128 cols, 4 q/thread ---
        const int kp0 = k0 >> 3;                    // first packed row
#pragma unroll
        for (int t = 0; t < 4; t++) {
            const int e  = tid + t * 256;           // 0..1023
            const int pr = e >> 7;                  // packed row 0..7
            const int q  = qweight[(size_t)(kp0 + pr) * N_DIM + gcol];
#pragma unroll
            for (int j = 0; j < 8; j++) {
                const int v = ((q >> (4 * j)) & 0xF) - zero;
                sB[(pr * 8 + j) * LDB + col] = __hmul(__int2half_rn(v), s);
            }
        }
        __syncthreads();

#pragma unroll
        for (int kk = 0; kk < BK; kk += 16) {
            wmma::fragment<wmma::matrix_a, 16, 16, 16, __half, wmma::row_major> fa[4];
            wmma::fragment<wmma::matrix_b, 16, 16, 16, __half, wmma::row_major> fb[2];
#pragma unroll
            for (int i = 0; i < 4; i++)
                wmma::load_matrix_sync(fa[i], &sA[(wm * 64 + i * 16) * LDA + kk], LDA);
#pragma unroll
            for (int j = 0; j < 2; j++)
                wmma::load_matrix_sync(fb[j], &sB[kk * LDB + wn * 32 + j * 16], LDB);
#pragma unroll
            for (int i = 0; i < 4; i++)
#pragma unroll
                for (int j = 0; j < 2; j++)
                    wmma::mma_sync(acc[i][j], fa[i], fb[j], acc[i][j]);
        }
        __syncthreads();
    }

    // --- Epilogue: stage fp32 accum in smem (reuse sA), round via fp16,
    //     store float32 output ---
    float* stage = reinterpret_cast<float*>(sA) + warp * 256;  // 8 KB total
#pragma unroll
    for (int i = 0; i < 4; i++) {
#pragma unroll
        for (int j = 0; j < 2; j++) {
            wmma::store_matrix_sync(stage, acc[i][j], 16, wmma::mem_row_major);
            __syncwarp();
            const int gr = bm + wm * 64 + i * 16;
            const int gc = bn + wn * 32 + j * 16;
#pragma unroll
            for (int t = 0; t < 4; t++) {
                const int e = t * 64 + lane * 2;   // pairs cover 0..255
                const int r = e >> 4;
                const int c = e & 15;
                float2 o;
                o.x = __half2float(__float2half_rn(stage[e]));
                o.y = __half2float(__float2half_rn(stage[e + 1]));
                *reinterpret_cast<float2*>(Y + (size_t)(gr + r) * N_DIM + gc + c) = o;
            }
            __syncwarp();
        }
    }
}

// ---------------------------------------------------------------------------
// Harness entry
// inputs (metadata order): x f32 [M,K], qweight i32 [K/8,N],
//                          qzeros i32 [1,N/8], scales f32 [1,N]
// output: f32 [M,N]
// ---------------------------------------------------------------------------
extern "C" void kernel_launch(void* const* d_in, const int* in_sizes, int n_in,
                              void* d_out, int out_size) {
    const float* x       = (const float*)d_in[0];
    const int*   qweight = (const int*)d_in[1];
    const int*   qzeros  = (const int*)d_in[2];
    const float* scales  = (const float*)d_in[3];
    float*       out     = (float*)d_out;

    dim3 grid(N_DIM / BN, M_DIM / BM);   // 86 x 32
    fused_gptq_gemm<<<grid, 256>>>(x, qweight, qzeros, scales, out);
}

// round 5
// speedup vs baseline: 1.9580x; 1.9580x over previous
#include <cuda_runtime.h>
#include <cuda_fp16.h>
#include <cstdint>
#include <cstddef>

// ---------------------------------------------------------------------------
// Fused GPTQ 4-bit dequant + fp16 GEMM via mma.sync (HMMA), sm_103 base arch
// (toolchain compiles at compute_103: tcgen05 is NOT available).
//
// HARNESS DTYPES (fp16 tensors materialized as float32):
//   x      : float32 [4096, 4096]
//   qweight: int32   [512, 11008]  nibble j (shift 4*j) -> k = kp*8 + j
//   qzeros : int32   [1, 1376]     nibble (n%8) -> zero for col n; +1 (GPTQ)
//   scales : float32 [1, 11008]
//   out    : float32 [4096, 11008]
//
// Pipeline:
//   pre-pass: X f32 -> f16 into g_Xh, K-PERMUTED within each 8-group:
//             local l <-> global (l>>1) + 4*(l&1), i.e. pairs (t, t+4).
//             This matches the cheap nibble extraction
//             ((q >> 4t) & 0x000F000F) | 0x64006400 -> half2 (nib_t, nib_{t+4}).
//             Same permutation on A and B => contraction unchanged.
//   GEMM: CTA tile 128x256x64, 8 warps (2m x 4n) of 64x64,
//         A via cp.async.cg (16B) double-buffered, B dequant->STS,
//         ldmatrix (non-trans, both operands [outer][k] 128B SW128 rows),
//         mma.sync.m16n8k16 f32 accum; output rounded through fp16.
// ---------------------------------------------------------------------------

static constexpr int M_DIM = 4096;
static constexpr int K_DIM = 4096;
static constexpr int N_DIM = 11008;

static constexpr int BM = 128;
static constexpr int BN = 256;
static constexpr int BK = 64;                    // halves (128 B)
static constexpr int CHUNKS = K_DIM / BK;        // 64

// dynamic smem: A 2x16KB, B 2x32KB
static constexpr uint32_t A_SZ = BM * 128;       // 16384 B per stage
static constexpr uint32_t B_SZ = BN * 128;       // 32768 B per stage
static constexpr uint32_t SMEM_BYTES = 2 * A_SZ + 2 * B_SZ;  // 98304

__device__ __half g_Xh[(size_t)M_DIM * K_DIM];   // 32 MB scratch (static)

// ---------------- helpers ----------------
__device__ __forceinline__ uint32_t h2u(__half2 h) { return *reinterpret_cast<uint32_t*>(&h); }
__device__ __forceinline__ __half2  u2h(uint32_t u) { return *reinterpret_cast<__half2*>(&u); }
__device__ __forceinline__ float    rnd16(float x) { return __half2float(__float2half_rn(x)); }

__device__ __forceinline__ void cp16(uint32_t dst, const void* src) {
    asm volatile("cp.async.cg.shared.global [%0], [%1], 16;" :: "r"(dst), "l"(src));
}
__device__ __forceinline__ void ldsm4(uint32_t* r, uint32_t addr) {
    asm volatile("ldmatrix.sync.aligned.m8n8.x4.shared.b16 {%0,%1,%2,%3}, [%4];"
                 : "=r"(r[0]), "=r"(r[1]), "=r"(r[2]), "=r"(r[3]) : "r"(addr));
}
__device__ __forceinline__ void mma16816(float* c, const uint32_t* a,
                                         uint32_t b0, uint32_t b1) {
    asm volatile("mma.sync.aligned.m16n8k16.row.col.f32.f16.f16.f32 "
                 "{%0,%1,%2,%3}, {%4,%5,%6,%7}, {%8,%9}, {%0,%1,%2,%3};"
                 : "+f"(c[0]), "+f"(c[1]), "+f"(c[2]), "+f"(c[3])
                 : "r"(a[0]), "r"(a[1]), "r"(a[2]), "r"(a[3]), "r"(b0), "r"(b1));
}

// ---------------------------------------------------------------------------
// Pre-pass: f32 -> f16 with per-8-group K permutation (pairs (t, t+4)).
// One thread per 8-element group; fully coalesced 16B loads/stores.
// ---------------------------------------------------------------------------
__global__ void __launch_bounds__(256)
convert_x(const float* __restrict__ X) {
    const size_t e = (size_t)blockIdx.x * blockDim.x + threadIdx.x;
    if (e >= (size_t)M_DIM * (K_DIM / 8)) return;
    const float4* s = reinterpret_cast<const float4*>(X) + e * 2;
    const float4 lo = s[0];
    const float4 hi = s[1];
    uint4 o;
    o.x = h2u(__floats2half2_rn(lo.x, hi.x));
    o.y = h2u(__floats2half2_rn(lo.y, hi.y));
    o.z = h2u(__floats2half2_rn(lo.z, hi.z));
    o.w = h2u(__floats2half2_rn(lo.w, hi.w));
    reinterpret_cast<uint4*>(g_Xh)[e] = o;
}

// ---------------------------------------------------------------------------
__global__ void __launch_bounds__(256, 1)
gemm_mma(const int*   __restrict__ qweight,
         const int*   __restrict__ qzeros,
         const float* __restrict__ scales,
         float*       __restrict__ Y) {
    extern __shared__ char smem[];
    const uint32_t sb = (uint32_t)__cvta_generic_to_shared(smem);
    const uint32_t aOff[2] = {0u, A_SZ};
    const uint32_t bOff[2] = {2 * A_SZ, 2 * A_SZ + B_SZ};

    const int tid  = threadIdx.x;
    const int warp = tid >> 5;
    const int lane = tid & 31;
    const int wm   = warp >> 2;      // 0..1
    const int wn   = warp & 3;       // 0..3
    const int bm   = blockIdx.y * BM;
    const int bn   = blockIdx.x * BN;

    // dequant constants: one column per thread (BN == blockDim.x)
    const int gcol = bn + tid;
    const int zraw = (qzeros[gcol >> 3] >> ((gcol & 7) * 4)) & 0xF;
    const __half2 s2v = __half2half2(__float2half_rn(scales[gcol]));
    const __half2 z2  = __half2half2(__float2half_rn((float)(1025 + zraw)));
    const int* qcol = qweight + gcol;

    float acc[4][8][4];
#pragma unroll
    for (int i = 0; i < 4; ++i)
#pragma unroll
        for (int j = 0; j < 8; ++j)
#pragma unroll
            for (int t = 0; t < 4; ++t) acc[i][j][t] = 0.0f;

    // ---- prologue: A chunk 0 + q chunk 0 ----
#pragma unroll
    for (int i = 0; i < 4; ++i) {
        const int e = tid + i * 256;
        const int r = e >> 3, g = e & 7;
        const uint32_t dst = sb + aOff[0] +
            (uint32_t)(r * 128 + ((g * 16) ^ ((r & 7) << 4)));
        cp16(dst, g_Xh + (size_t)(bm + r) * K_DIM + g * 8);
    }
    asm volatile("cp.async.commit_group;" ::: "memory");
    uint32_t q[8];
#pragma unroll
    for (int pr = 0; pr < 8; ++pr)
        q[pr] = (uint32_t)qcol[(size_t)pr * N_DIM];

    for (int c = 0; c < CHUNKS; ++c) {
        const int buf = c & 1;

        // ---- dequant B(c) -> STS ----
        {
            const uint32_t bB   = sb + bOff[buf];
            const uint32_t brow = (uint32_t)tid * 128;
            const uint32_t bx   = (uint32_t)(tid & 7) << 4;
#pragma unroll
            for (int pr = 0; pr < 8; ++pr) {
                const uint32_t w = q[pr];
                uint32_t u[4];
#pragma unroll
                for (int t = 0; t < 4; ++t) {
                    const uint32_t hb = ((w >> (4 * t)) & 0x000F000Fu) | 0x64006400u;
                    u[t] = h2u(__hmul2(__hsub2(u2h(hb), z2), s2v));
                }
                const uint32_t dst = bB + brow + (((uint32_t)pr * 16) ^ bx);
                asm volatile("st.shared.v4.b32 [%0], {%1,%2,%3,%4};"
                             :: "r"(dst), "r"(u[0]), "r"(u[1]), "r"(u[2]), "r"(u[3])
                             : "memory");
            }
        }

        // ---- prefetch chunk c+1 (A via cp.async, q via LDG) ----
        if (c + 1 < CHUNKS) {
            const uint32_t aB = sb + aOff[buf ^ 1];
            const int k0 = (c + 1) * BK;
#pragma unroll
            for (int i = 0; i < 4; ++i) {
                const int e = tid + i * 256;
                const int r = e >> 3, g = e & 7;
                const uint32_t dst = aB +
                    (uint32_t)(r * 128 + ((g * 16) ^ ((r & 7) << 4)));
                cp16(dst, g_Xh + (size_t)(bm + r) * K_DIM + k0 + g * 8);
            }
            asm volatile("cp.async.commit_group;" ::: "memory");
#pragma unroll
            for (int pr = 0; pr < 8; ++pr)
                q[pr] = (uint32_t)qcol[(size_t)((c + 1) * 8 + pr) * N_DIM];
            asm volatile("cp.async.wait_group 1;" ::: "memory");
        } else {
            asm volatile("cp.async.wait_group 0;" ::: "memory");
        }
        __syncthreads();   // A(c) + B(c) visible

        // ---- MMA over stage buf ----
        const uint32_t aB = sb + aOff[buf];
        const uint32_t bB = sb + bOff[buf];
#pragma unroll
        for (int kk = 0; kk < 4; ++kk) {
            const uint32_t kb = kk * 32;
            uint32_t a[4][4], b[4][4];
#pragma unroll
            for (int j = 0; j < 4; ++j) {
                const int row = wn * 64 + j * 16 + ((lane >> 4) << 3) + (lane & 7);
                const uint32_t addr = bB + row * 128 +
                    ((kb + (((lane >> 3) & 1) << 4)) ^ ((row & 7) << 4));
                ldsm4(b[j], addr);
            }
#pragma unroll
            for (int i = 0; i < 4; ++i) {
                const int row = wm * 64 + i * 16 + (lane & 15);
                const uint32_t addr = aB + row * 128 +
                    ((kb + ((lane >> 4) << 4)) ^ ((row & 7) << 4));
                ldsm4(a[i], addr);
            }
#pragma unroll
            for (int i = 0; i < 4; ++i)
#pragma unroll
                for (int j = 0; j < 4; ++j) {
                    mma16816(acc[i][2 * j],     a[i], b[j][0], b[j][1]);
                    mma16816(acc[i][2 * j + 1], a[i], b[j][2], b[j][3]);
                }
        }
        __syncthreads();   // all reads of stage buf done before reuse
    }

    // ---- epilogue: round via fp16, store f32 ----
#pragma unroll
    for (int i = 0; i < 4; ++i) {
        const int m0 = bm + wm * 64 + i * 16 + (lane >> 2);
        float* y0 = Y + (size_t)m0 * N_DIM;
        float* y1 = y0 + (size_t)8 * N_DIM;
#pragma unroll
        for (int jj = 0; jj < 8; ++jj) {
            const int n0 = bn + wn * 64 + jj * 8 + 2 * (lane & 3);
            float2 v0, v1;
            v0.x = rnd16(acc[i][jj][0]);
            v0.y = rnd16(acc[i][jj][1]);
            v1.x = rnd16(acc[i][jj][2]);
            v1.y = rnd16(acc[i][jj][3]);
            *reinterpret_cast<float2*>(y0 + n0) = v0;
            *reinterpret_cast<float2*>(y1 + n0) = v1;
        }
    }
}

// ---------------------------------------------------------------------------
extern "C" void kernel_launch(void* const* d_in, const int* in_sizes, int n_in,
                              void* d_out, int out_size) {
    const float* x       = (const float*)d_in[0];
    const int*   qweight = (const int*)d_in[1];
    const int*   qzeros  = (const int*)d_in[2];
    const float* scales  = (const float*)d_in[3];
    float*       out     = (float*)d_out;

    cudaFuncSetAttribute(gemm_mma,
                         cudaFuncAttributeMaxDynamicSharedMemorySize, SMEM_BYTES);

    const int groups = M_DIM * (K_DIM / 8);
    convert_x<<<(groups + 255) / 256, 256>>>(x);

    dim3 grid(N_DIM / BN, M_DIM / BM);   // 43 x 32
    gemm_mma<<<grid, 256, SMEM_BYTES>>>(qweight, qzeros, scales, out);
}

// round 6
// speedup vs baseline: 2.3104x; 1.1800x over previous
#include <cuda_runtime.h>
#include <cuda_fp16.h>
#include <cstdint>
#include <cstddef>

// ---------------------------------------------------------------------------
// Fused GPTQ 4-bit dequant + fp16 GEMM via mma.sync (HMMA), sm_103 base arch
// (toolchain compiles at compute_103: tcgen05 unavailable).
//
// R6 change vs R5: CTA tile 128x256 -> 128x128 (warp tile 64x64 -> 64x32),
// regs capped for 2 CTAs/SM (__launch_bounds__(256,2), 64KB smem/CTA).
// The producer phase + barriers of one CTA overlap the MMA phase of the
// co-resident CTA, filling the ~45% tensor-pipe bubble seen in R5.
//
//   x      : float32 [4096, 4096]
//   qweight: int32   [512, 11008]  nibble j (shift 4*j) -> k = kp*8 + j
//   qzeros : int32   [1, 1376]     nibble (n%8) -> zero for col n; +1 (GPTQ)
//   scales : float32 [1, 11008]
//   out    : float32 [4096, 11008]
//
// Pre-pass: X f32 -> f16 into g_Xh, K-permuted within each 8-group
// (pairs (t, t+4)) to match the cheap nibble extraction
// ((q >> 4t) & 0x000F000F) | 0x64006400. Same permutation on A and B
// => contraction unchanged.
// ---------------------------------------------------------------------------

static constexpr int M_DIM = 4096;
static constexpr int K_DIM = 4096;
static constexpr int N_DIM = 11008;

static constexpr int BM = 128;
static constexpr int BN = 128;
static constexpr int BK = 64;                    // halves (128 B)
static constexpr int CHUNKS = K_DIM / BK;        // 64

// dynamic smem: A 2x16KB, B 2x16KB = 64 KB (2 CTAs/SM -> 128 KB/SM)
static constexpr uint32_t A_SZ = BM * 128;       // 16384 B per stage
static constexpr uint32_t B_SZ = BN * 128;       // 16384 B per stage
static constexpr uint32_t SMEM_BYTES = 2 * A_SZ + 2 * B_SZ;  // 65536

__device__ __half g_Xh[(size_t)M_DIM * K_DIM];   // 32 MB scratch (static)

// ---------------- helpers ----------------
__device__ __forceinline__ uint32_t h2u(__half2 h) { return *reinterpret_cast<uint32_t*>(&h); }
__device__ __forceinline__ __half2  u2h(uint32_t u) { return *reinterpret_cast<__half2*>(&u); }
__device__ __forceinline__ float    rnd16(float x) { return __half2float(__float2half_rn(x)); }

__device__ __forceinline__ void cp16(uint32_t dst, const void* src) {
    asm volatile("cp.async.cg.shared.global [%0], [%1], 16;" :: "r"(dst), "l"(src));
}
__device__ __forceinline__ void ldsm4(uint32_t* r, uint32_t addr) {
    asm volatile("ldmatrix.sync.aligned.m8n8.x4.shared.b16 {%0,%1,%2,%3}, [%4];"
                 : "=r"(r[0]), "=r"(r[1]), "=r"(r[2]), "=r"(r[3]) : "r"(addr));
}
__device__ __forceinline__ void mma16816(float* c, const uint32_t* a,
                                         uint32_t b0, uint32_t b1) {
    asm volatile("mma.sync.aligned.m16n8k16.row.col.f32.f16.f16.f32 "
                 "{%0,%1,%2,%3}, {%4,%5,%6,%7}, {%8,%9}, {%0,%1,%2,%3};"
                 : "+f"(c[0]), "+f"(c[1]), "+f"(c[2]), "+f"(c[3])
                 : "r"(a[0]), "r"(a[1]), "r"(a[2]), "r"(a[3]), "r"(b0), "r"(b1));
}

// ---------------------------------------------------------------------------
// Pre-pass: f32 -> f16 with per-8-group K permutation (pairs (t, t+4)).
// ---------------------------------------------------------------------------
__global__ void __launch_bounds__(256)
convert_x(const float* __restrict__ X) {
    const size_t e = (size_t)blockIdx.x * blockDim.x + threadIdx.x;
    if (e >= (size_t)M_DIM * (K_DIM / 8)) return;
    const float4* s = reinterpret_cast<const float4*>(X) + e * 2;
    const float4 lo = s[0];
    const float4 hi = s[1];
    uint4 o;
    o.x = h2u(__floats2half2_rn(lo.x, hi.x));
    o.y = h2u(__floats2half2_rn(lo.y, hi.y));
    o.z = h2u(__floats2half2_rn(lo.z, hi.z));
    o.w = h2u(__floats2half2_rn(lo.w, hi.w));
    reinterpret_cast<uint4*>(g_Xh)[e] = o;
}

// ---------------------------------------------------------------------------
__global__ void __launch_bounds__(256, 2)
gemm_mma(const int*   __restrict__ qweight,
         const int*   __restrict__ qzeros,
         const float* __restrict__ scales,
         float*       __restrict__ Y) {
    extern __shared__ char smem[];
    const uint32_t sb = (uint32_t)__cvta_generic_to_shared(smem);
    const uint32_t aOff[2] = {0u, A_SZ};
    const uint32_t bOff[2] = {2 * A_SZ, 2 * A_SZ + B_SZ};

    const int tid  = threadIdx.x;
    const int warp = tid >> 5;
    const int lane = tid & 31;
    const int wm   = warp >> 2;      // 0..1  (64-row slice)
    const int wn   = warp & 3;       // 0..3  (32-col slice)
    const int bm   = blockIdx.y * BM;
    const int bn   = blockIdx.x * BN;

    // dequant mapping: 2 threads per column, 4 packed rows each
    const int nloc = tid & 127;                 // column 0..127
    const int half = tid >> 7;                  // 0: pr 0-3, 1: pr 4-7
    const int gcol = bn + nloc;
    const int zraw = (qzeros[gcol >> 3] >> ((gcol & 7) * 4)) & 0xF;
    const __half2 s2v = __half2half2(__float2half_rn(scales[gcol]));
    const __half2 z2  = __half2half2(__float2half_rn((float)(1025 + zraw)));
    const int* qcol = qweight + (size_t)half * 4 * N_DIM + gcol;

    float acc[4][4][4];
#pragma unroll
    for (int i = 0; i < 4; ++i)
#pragma unroll
        for (int j = 0; j < 4; ++j)
#pragma unroll
            for (int t = 0; t < 4; ++t) acc[i][j][t] = 0.0f;

    // ---- prologue: A chunk 0 + q chunk 0 ----
#pragma unroll
    for (int i = 0; i < 4; ++i) {
        const int e = tid + i * 256;
        const int r = e >> 3, g = e & 7;
        const uint32_t dst = sb + aOff[0] +
            (uint32_t)(r * 128 + ((g * 16) ^ ((r & 7) << 4)));
        cp16(dst, g_Xh + (size_t)(bm + r) * K_DIM + g * 8);
    }
    asm volatile("cp.async.commit_group;" ::: "memory");
    uint32_t q[4];
#pragma unroll
    for (int pr = 0; pr < 4; ++pr)
        q[pr] = (uint32_t)qcol[(size_t)pr * N_DIM];

    for (int c = 0; c < CHUNKS; ++c) {
        const int buf = c & 1;

        // ---- dequant B(c) -> STS (4 packed rows per thread) ----
        {
            const uint32_t bB   = sb + bOff[buf];
            const uint32_t brow = (uint32_t)nloc * 128;
            const uint32_t bx   = (uint32_t)(nloc & 7) << 4;
#pragma unroll
            for (int pr = 0; pr < 4; ++pr) {
                const uint32_t w = q[pr];
                uint32_t u[4];
#pragma unroll
                for (int t = 0; t < 4; ++t) {
                    const uint32_t hb = ((w >> (4 * t)) & 0x000F000Fu) | 0x64006400u;
                    u[t] = h2u(__hmul2(__hsub2(u2h(hb), z2), s2v));
                }
                const uint32_t dst = bB + brow +
                    ((((uint32_t)(half * 4 + pr)) * 16) ^ bx);
                asm volatile("st.shared.v4.b32 [%0], {%1,%2,%3,%4};"
                             :: "r"(dst), "r"(u[0]), "r"(u[1]), "r"(u[2]), "r"(u[3])
                             : "memory");
            }
        }

        // ---- prefetch chunk c+1 (A via cp.async, q via LDG) ----
        if (c + 1 < CHUNKS) {
            const uint32_t aB = sb + aOff[buf ^ 1];
            const int k0 = (c + 1) * BK;
#pragma unroll
            for (int i = 0; i < 4; ++i) {
                const int e = tid + i * 256;
                const int r = e >> 3, g = e & 7;
                const uint32_t dst = aB +
                    (uint32_t)(r * 128 + ((g * 16) ^ ((r & 7) << 4)));
                cp16(dst, g_Xh + (size_t)(bm + r) * K_DIM + k0 + g * 8);
            }
            asm volatile("cp.async.commit_group;" ::: "memory");
#pragma unroll
            for (int pr = 0; pr < 4; ++pr)
                q[pr] = (uint32_t)qcol[(size_t)((c + 1) * 8 + pr) * N_DIM];
            asm volatile("cp.async.wait_group 1;" ::: "memory");
        } else {
            asm volatile("cp.async.wait_group 0;" ::: "memory");
        }
        __syncthreads();   // A(c) + B(c) visible

        // ---- MMA over stage buf: warp tile 64(m) x 32(n) ----
        const uint32_t aB = sb + aOff[buf];
        const uint32_t bB = sb + bOff[buf];
#pragma unroll
        for (int kk = 0; kk < 4; ++kk) {
            const uint32_t kb = kk * 32;
            uint32_t a[4][4], b[2][4];
#pragma unroll
            for (int j = 0; j < 2; ++j) {
                const int row = wn * 32 + j * 16 + ((lane >> 4) << 3) + (lane & 7);
                const uint32_t addr = bB + row * 128 +
                    ((kb + (((lane >> 3) & 1) << 4)) ^ ((row & 7) << 4));
                ldsm4(b[j], addr);
            }
#pragma unroll
            for (int i = 0; i < 4; ++i) {
                const int row = wm * 64 + i * 16 + (lane & 15);
                const uint32_t addr = aB + row * 128 +
                    ((kb + ((lane >> 4) << 4)) ^ ((row & 7) << 4));
                ldsm4(a[i], addr);
            }
#pragma unroll
            for (int i = 0; i < 4; ++i)
#pragma unroll
                for (int j = 0; j < 2; ++j) {
                    mma16816(acc[i][2 * j],     a[i], b[j][0], b[j][1]);
                    mma16816(acc[i][2 * j + 1], a[i], b[j][2], b[j][3]);
                }
        }
        __syncthreads();   // all reads of stage buf done before reuse
    }

    // ---- epilogue: round via fp16, store f32 ----
#pragma unroll
    for (int i = 0; i < 4; ++i) {
        const int m0 = bm + wm * 64 + i * 16 + (lane >> 2);
        float* y0 = Y + (size_t)m0 * N_DIM;
        float* y1 = y0 + (size_t)8 * N_DIM;
#pragma unroll
        for (int jj = 0; jj < 4; ++jj) {
            const int n0 = bn + wn * 32 + jj * 8 + 2 * (lane & 3);
            float2 v0, v1;
            v0.x = rnd16(acc[i][jj][0]);
            v0.y = rnd16(acc[i][jj][1]);
            v1.x = rnd16(acc[i][jj][2]);
            v1.y = rnd16(acc[i][jj][3]);
            *reinterpret_cast<float2*>(y0 + n0) = v0;
            *reinterpret_cast<float2*>(y1 + n0) = v1;
        }
    }
}

// ---------------------------------------------------------------------------
extern "C" void kernel_launch(void* const* d_in, const int* in_sizes, int n_in,
                              void* d_out, int out_size) {
    const float* x       = (const float*)d_in[0];
    const int*   qweight = (const int*)d_in[1];
    const int*   qzeros  = (const int*)d_in[2];
    const float* scales  = (const float*)d_in[3];
    float*       out     = (float*)d_out;

    cudaFuncSetAttribute(gemm_mma,
                         cudaFuncAttributeMaxDynamicSharedMemorySize, SMEM_BYTES);

    const int groups = M_DIM * (K_DIM / 8);
    convert_x<<<(groups + 255) / 256, 256>>>(x);

    dim3 grid(N_DIM / BN, M_DIM / BM);   // 86 x 32
    gemm_mma<<<grid, 256, SMEM_BYTES>>>(qweight, qzeros, scales, out);
}